// round 1
// baseline (speedup 1.0000x reference)
#include <cuda_runtime.h>
#include <cuda_bf16.h>
#include <math.h>

// Problem dims (fixed by dataset)
#define Bb 64
#define Cc 64
#define Dd 512
#define Oo 256
#define NREG 8
#define Gg 8
#define Mrows (Bb*Cc)   // 4096

// Scratch (device globals; no allocation allowed)
__device__ float g_a [Mrows*Dd];   // x @ W1a              8 MB
__device__ float g_bp[Mrows*Dd];   // x @ W1b + b1         8 MB
__device__ float g_m [Mrows*Dd];   // m1 then m2           8 MB
__device__ float g_x1[Mrows*Dd];   // x1                   8 MB
__device__ float g_w [Bb*NREG*Gg*Gg]; // adj weights       128 KB

// ---------------------------------------------------------------------------
// SGEMM: C[M,N] = epilogue(A[M,K] @ B[K,N] + bias[N])
// BM=128, BN=64, BK=16, 256 threads, 8x4 microtile.
// lda == K, ldb == N, ldc == N (true for all our GEMMs).
// MODE 0: + bias (bias may be null)
// MODE 1: leaky_relu(0.2)
// MODE 2: 0.5*leaky(z) + 0.5*res[m,n]
// ---------------------------------------------------------------------------
template<int MODE>
__global__ __launch_bounds__(256, 2)
void sgemm_kernel(const float* __restrict__ A, const float* __restrict__ Bm,
                  const float* __restrict__ bias, const float* __restrict__ res,
                  float* __restrict__ C, int M, int N, int K)
{
    constexpr int BM = 128, BN = 64, BK = 16;
    __shared__ float As[BK][BM + 4];
    __shared__ float Bs[BK][BN];

    const int tid = threadIdx.x;
    const int tx = tid & 15;   // 0..15 col group (4 cols each)
    const int ty = tid >> 4;   // 0..15 row group (8 rows each)
    const int row0 = blockIdx.y * BM;
    const int col0 = blockIdx.x * BN;

    float acc[8][4];
    #pragma unroll
    for (int i = 0; i < 8; i++)
        #pragma unroll
        for (int j = 0; j < 4; j++) acc[i][j] = 0.f;

    for (int kt = 0; kt < K; kt += BK) {
        // Load A tile: 128x16 = 512 float4, 2 per thread, store transposed
        #pragma unroll
        for (int i = 0; i < 2; i++) {
            int id = tid * 2 + i;
            int r  = id >> 2;            // 0..127
            int kk = (id & 3) << 2;      // 0,4,8,12
            float4 v = *(const float4*)(A + (size_t)(row0 + r) * K + kt + kk);
            As[kk + 0][r] = v.x;
            As[kk + 1][r] = v.y;
            As[kk + 2][r] = v.z;
            As[kk + 3][r] = v.w;
        }
        // Load B tile: 16x64 = 256 float4, 1 per thread
        {
            int r = tid >> 4;            // 0..15
            int c = (tid & 15) << 2;     // 0..60
            *(float4*)&Bs[r][c] = *(const float4*)(Bm + (size_t)(kt + r) * N + col0 + c);
        }
        __syncthreads();

        #pragma unroll
        for (int k = 0; k < BK; k++) {
            float ar[8], br[4];
            float4 a0 = *(const float4*)&As[k][ty * 8];
            float4 a1 = *(const float4*)&As[k][ty * 8 + 4];
            ar[0]=a0.x; ar[1]=a0.y; ar[2]=a0.z; ar[3]=a0.w;
            ar[4]=a1.x; ar[5]=a1.y; ar[6]=a1.z; ar[7]=a1.w;
            float4 b0 = *(const float4*)&Bs[k][tx * 4];
            br[0]=b0.x; br[1]=b0.y; br[2]=b0.z; br[3]=b0.w;
            #pragma unroll
            for (int i = 0; i < 8; i++)
                #pragma unroll
                for (int j = 0; j < 4; j++)
                    acc[i][j] = fmaf(ar[i], br[j], acc[i][j]);
        }
        __syncthreads();
    }

    // Epilogue
    #pragma unroll
    for (int i = 0; i < 8; i++) {
        int r = row0 + ty * 8 + i;
        int cbase = col0 + tx * 4;
        float4 out;
        float* o = &out.x;
        #pragma unroll
        for (int j = 0; j < 4; j++) {
            int c = cbase + j;
            float v = acc[i][j];
            if (bias) v += bias[c];
            if (MODE >= 1) v = (v >= 0.f) ? v : 0.2f * v;
            if (MODE == 2) v = 0.5f * v + 0.5f * res[(size_t)r * N + c];
            o[j] = v;
        }
        *(float4*)(C + (size_t)r * N + cbase) = out;
    }
}

// ---------------------------------------------------------------------------
// Attention: per (batch, region) block computes 8x8 masked softmax weights.
// scores[i][j] = sum_d relu(a[i,d] + bp[j,d]) * W2[d] + b2   (b1 folded in bp)
// ---------------------------------------------------------------------------
__global__ __launch_bounds__(256)
void attn_kernel(const float* __restrict__ a, const float* __restrict__ bp,
                 const float* __restrict__ W2, const float* __restrict__ b2,
                 const int* __restrict__ ridx, float* __restrict__ wout)
{
    __shared__ float sa[Gg][Dd];
    __shared__ float sb[Gg][Dd];
    __shared__ float sw2[Dd];
    __shared__ float ssc[Gg][Gg];
    __shared__ int   ch[Gg];

    const int tid  = threadIdx.x;
    const int blk  = blockIdx.x;           // 0..511
    const int b    = blk >> 3;
    const int r    = blk & 7;

    if (tid < Gg) ch[tid] = ridx[r * Gg + tid];
    __syncthreads();

    for (int d = tid; d < Dd; d += 256) sw2[d] = W2[d];
    #pragma unroll
    for (int j = 0; j < Gg; j++) {
        const float* arow = a  + (size_t)(b * Cc + ch[j]) * Dd;
        const float* brow = bp + (size_t)(b * Cc + ch[j]) * Dd;
        for (int d = tid; d < Dd; d += 256) {
            sa[j][d] = arow[d];
            sb[j][d] = brow[d];
        }
    }
    __syncthreads();

    // 8 warps, warp w == row i; each warp computes scores[i][0..7]
    const int wid  = tid >> 5;
    const int lane = tid & 31;
    float accq[Gg];
    #pragma unroll
    for (int q = 0; q < Gg; q++) accq[q] = 0.f;
    for (int t = lane; t < Dd; t += 32) {
        float av = sa[wid][t];
        float wv = sw2[t];
        #pragma unroll
        for (int q = 0; q < Gg; q++) {
            float v = av + sb[q][t];
            v = fmaxf(v, 0.f);
            accq[q] = fmaf(v, wv, accq[q]);
        }
    }
    #pragma unroll
    for (int q = 0; q < Gg; q++) {
        #pragma unroll
        for (int off = 16; off > 0; off >>= 1)
            accq[q] += __shfl_xor_sync(0xffffffffu, accq[q], off);
    }
    if (lane == 0) {
        float bb2 = b2[0];
        #pragma unroll
        for (int q = 0; q < Gg; q++) ssc[wid][q] = accq[q] + bb2;
    }
    __syncthreads();

    // Softmax per row, excluding diagonal
    if (tid < Gg) {
        int i = tid;
        float mx = -1e30f;
        #pragma unroll
        for (int j = 0; j < Gg; j++)
            if (j != i) mx = fmaxf(mx, ssc[i][j]);
        float e[Gg]; float s = 0.f;
        #pragma unroll
        for (int j = 0; j < Gg; j++) {
            e[j] = (j == i) ? 0.f : __expf(ssc[i][j] - mx);
            s += e[j];
        }
        float inv = 1.f / s;
        float* wrow = wout + ((size_t)blk * Gg + i) * Gg;
        #pragma unroll
        for (int j = 0; j < Gg; j++) wrow[j] = e[j] * inv;
    }
}

// ---------------------------------------------------------------------------
// Aggregation: m[b, ch_i, :] = sum_j w[b,r,i,j] * xin[b, ch_j, :]
// ---------------------------------------------------------------------------
__global__ __launch_bounds__(256)
void agg_kernel(const float* __restrict__ w, const float* __restrict__ xin,
                const int* __restrict__ ridx, float* __restrict__ mout)
{
    __shared__ float xs[Gg][Dd];
    __shared__ float ww[Gg * Gg];
    __shared__ int   ch[Gg];

    const int tid = threadIdx.x;
    const int blk = blockIdx.x;
    const int b   = blk >> 3;
    const int r   = blk & 7;

    if (tid < Gg) ch[tid] = ridx[r * Gg + tid];
    if (tid >= 32 && tid < 96) ww[tid - 32] = w[(size_t)blk * 64 + (tid - 32)];
    __syncthreads();

    #pragma unroll
    for (int j = 0; j < Gg; j++) {
        const float* xrow = xin + (size_t)(b * Cc + ch[j]) * Dd;
        for (int d = tid; d < Dd; d += 256) xs[j][d] = xrow[d];
    }
    __syncthreads();

    #pragma unroll
    for (int i = 0; i < Gg; i++) {
        float* orow = mout + (size_t)(b * Cc + ch[i]) * Dd;
        float wi[Gg];
        #pragma unroll
        for (int j = 0; j < Gg; j++) wi[j] = ww[i * Gg + j];
        for (int d = tid; d < Dd; d += 256) {
            float accv = 0.f;
            #pragma unroll
            for (int j = 0; j < Gg; j++) accv = fmaf(wi[j], xs[j][d], accv);
            orow[d] = accv;
        }
    }
}

// ---------------------------------------------------------------------------
extern "C" void kernel_launch(void* const* d_in, const int* in_sizes, int n_in,
                              void* d_out, int out_size)
{
    const float* x    = (const float*)d_in[0];
    const float* W1   = (const float*)d_in[1];
    const float* b1   = (const float*)d_in[2];
    const float* W2   = (const float*)d_in[3];
    const float* b2   = (const float*)d_in[4];
    const float* Wg1  = (const float*)d_in[5];
    const float* bg1  = (const float*)d_in[6];
    const float* Wg2  = (const float*)d_in[7];
    const float* bg2  = (const float*)d_in[8];
    const int*   ridx = (const int*)d_in[9];
    float* out = (float*)d_out;

    float *ga, *gbp, *gm, *gx1, *gw;
    cudaGetSymbolAddress((void**)&ga,  g_a);
    cudaGetSymbolAddress((void**)&gbp, g_bp);
    cudaGetSymbolAddress((void**)&gm,  g_m);
    cudaGetSymbolAddress((void**)&gx1, g_x1);
    cudaGetSymbolAddress((void**)&gw,  g_w);

    dim3 blk(256);

    // G1a: a = x @ W1[:D]          (M=4096, N=512, K=512)
    {
        dim3 grid(Dd / 64, Mrows / 128);
        sgemm_kernel<0><<<grid, blk>>>(x, W1, nullptr, nullptr, ga, Mrows, Dd, Dd);
    }
    // G1b: bp = x @ W1[D:] + b1
    {
        dim3 grid(Dd / 64, Mrows / 128);
        sgemm_kernel<0><<<grid, blk>>>(x, W1 + (size_t)Dd * Dd, b1, nullptr, gbp, Mrows, Dd, Dd);
    }
    // Attention weights
    attn_kernel<<<Bb * NREG, blk>>>(ga, gbp, W2, b2, ridx, gw);
    // m1 = adj @ x
    agg_kernel<<<Bb * NREG, blk>>>(gw, x, ridx, gm);
    // x1 = 0.5*leaky(m1 @ Wg1 + bg1) + 0.5*x
    {
        dim3 grid(Dd / 64, Mrows / 128);
        sgemm_kernel<2><<<grid, blk>>>(gm, Wg1, bg1, x, gx1, Mrows, Dd, Dd);
    }
    // m2 = adj @ x1
    agg_kernel<<<Bb * NREG, blk>>>(gw, gx1, ridx, gm);
    // out = leaky(m2 @ Wg2 + bg2)   (N=256)
    {
        dim3 grid(Oo / 64, Mrows / 128);
        sgemm_kernel<1><<<grid, blk>>>(gm, Wg2, bg2, nullptr, out, Mrows, Oo, Dd);
    }
}